// round 16
// baseline (speedup 1.0000x reference)
#include <cuda_runtime.h>
#include <cuda_bf16.h>
#include <stdint.h>
#include <math.h>

#define NUM_HEAD 16
#define D_MODEL 1024
#define HEAD_DIM 64
#define BATCH 2
#define SEQ 2048
#define MROWS (BATCH * SEQ)          // 4096
#define QKV_N (3 * D_MODEL)          // 3072

// ---------------- scratch (device globals: allocation-guard safe) ----------
__device__ __nv_bfloat16 g_qkvhi[(size_t)MROWS * QKV_N];
__device__ __nv_bfloat16 g_qkvlo[(size_t)MROWS * QKV_N];
__device__ __nv_bfloat16 g_xhi[(size_t)MROWS * D_MODEL];
__device__ __nv_bfloat16 g_xlo[(size_t)MROWS * D_MODEL];
__device__ __nv_bfloat16 g_wqT_hi[(size_t)QKV_N * D_MODEL];
__device__ __nv_bfloat16 g_wqT_lo[(size_t)QKV_N * D_MODEL];
__device__ __nv_bfloat16 g_woT_hi[(size_t)D_MODEL * D_MODEL];
__device__ __nv_bfloat16 g_woT_lo[(size_t)D_MODEL * D_MODEL];
__device__ __nv_bfloat16 g_ahi[(size_t)MROWS * D_MODEL];
__device__ __nv_bfloat16 g_alo[(size_t)MROWS * D_MODEL];

// ---------------- PTX helpers ----------------------------------------------
__device__ __forceinline__ uint32_t smem_u32(const void* p) {
    uint32_t a;
    asm("{ .reg .u64 t; cvta.to.shared.u64 t, %1; cvt.u32.u64 %0, t; }" : "=r"(a) : "l"(p));
    return a;
}
__device__ __forceinline__ void cp16(uint32_t dst, const void* src) {
    asm volatile("cp.async.cg.shared.global [%0], [%1], 16;" :: "r"(dst), "l"(src) : "memory");
}
#define CP_COMMIT() asm volatile("cp.async.commit_group;" ::: "memory")
#define CP_WAIT(n)  asm volatile("cp.async.wait_group %0;" :: "n"(n) : "memory")

#define LDSM4(r0, r1, r2, r3, addr) \
    asm volatile("ldmatrix.sync.aligned.m8n8.x4.shared.b16 {%0,%1,%2,%3}, [%4];" \
                 : "=r"(r0), "=r"(r1), "=r"(r2), "=r"(r3) : "r"(addr))
#define LDSM4T(r0, r1, r2, r3, addr) \
    asm volatile("ldmatrix.sync.aligned.m8n8.x4.trans.shared.b16 {%0,%1,%2,%3}, [%4];" \
                 : "=r"(r0), "=r"(r1), "=r"(r2), "=r"(r3) : "r"(addr))

#define MMA16816(d, a, b) \
    asm volatile("mma.sync.aligned.m16n8k16.row.col.f32.bf16.bf16.f32 " \
                 "{%0,%1,%2,%3},{%4,%5,%6,%7},{%8,%9},{%0,%1,%2,%3};" \
                 : "+f"((d)[0]), "+f"((d)[1]), "+f"((d)[2]), "+f"((d)[3]) \
                 : "r"((a)[0]), "r"((a)[1]), "r"((a)[2]), "r"((a)[3]), \
                   "r"((b)[0]), "r"((b)[1]))

__device__ __forceinline__ uint32_t packpair(float x, float y, uint32_t& lo) {
    __nv_bfloat16 hx = __float2bfloat16(x), hy = __float2bfloat16(y);
    __nv_bfloat162 h; h.x = hx; h.y = hy;
    __nv_bfloat162 l;
    l.x = __float2bfloat16(x - __bfloat162float(hx));
    l.y = __float2bfloat16(y - __bfloat162float(hy));
    lo = *(uint32_t*)&l;
    return *(uint32_t*)&h;
}

// ---------------------------------------------------------------------------
__global__ void decomp_kernel(const float* __restrict__ in,
                              __nv_bfloat16* __restrict__ hi,
                              __nv_bfloat16* __restrict__ lo, int n)
{
    int i = (blockIdx.x * blockDim.x + threadIdx.x) * 4;
    if (i >= n) return;
    float4 v = *(const float4*)(in + i);
    uint32_t l0, l1;
    uint32_t h0 = packpair(v.x, v.y, l0);
    uint32_t h1 = packpair(v.z, v.w, l1);
    *(uint32_t*)(hi + i) = h0; *(uint32_t*)(hi + i + 2) = h1;
    *(uint32_t*)(lo + i) = l0; *(uint32_t*)(lo + i + 2) = l1;
}

__global__ void transdecomp_kernel(const float* __restrict__ W,
                                   __nv_bfloat16* __restrict__ Thi,
                                   __nv_bfloat16* __restrict__ Tlo, int K, int N)
{
    __shared__ float tile[32][33];
    int n0 = blockIdx.x * 32, k0 = blockIdx.y * 32;
    #pragma unroll
    for (int i = 0; i < 4; i++)
        tile[threadIdx.y + i * 8][threadIdx.x] =
            W[(size_t)(k0 + threadIdx.y + i * 8) * N + n0 + threadIdx.x];
    __syncthreads();
    #pragma unroll
    for (int i = 0; i < 4; i++) {
        int n = n0 + threadIdx.y + i * 8;
        int k = k0 + threadIdx.x;
        float v = tile[threadIdx.x][threadIdx.y + i * 8];
        __nv_bfloat16 h = __float2bfloat16(v);
        Thi[(size_t)n * K + k] = h;
        Tlo[(size_t)n * K + k] = __float2bfloat16(v - __bfloat162float(h));
    }
}

// ---------------------------------------------------------------------------
// Persistent mma.sync bf16 hi/lo GEMM: C = A[M,K]@B[N,K]^T + bias.
// CTA tile 128x256, 256 threads (8 warps 2m x 4n, warp tile 64x64 as in the
// verified R7 kernel). Per-chunk barrier overhead amortized over 2x the MMAs.
// Verified load-first / double-barrier chunk loop: the trailing
// __syncthreads() protects the buffer the next chunk's prefetch overwrites.
// ---------------------------------------------------------------------------
#define RS 80
#define OFF_ALO 10240         // A: 128 rows * 80B
#define OFF_BHI 20480
#define OFF_BLO 40960         // B: 256 rows * 80B
#define STAGE_B 61440         // Ahi,Alo,Bhi,Blo
#define GEMM_SMEM 122880      // 2 stages

__global__ __launch_bounds__(256, 1)
void gemm_mma(const __nv_bfloat16* __restrict__ Ahi, const __nv_bfloat16* __restrict__ Alo,
              const __nv_bfloat16* __restrict__ Bhi, const __nv_bfloat16* __restrict__ Blo,
              const float* __restrict__ bias, float* __restrict__ C,
              __nv_bfloat16* __restrict__ Chi, __nv_bfloat16* __restrict__ Clo,
              int M, int N, int K)
{
    extern __shared__ char smem[];
    const uint32_t sb = smem_u32(smem);
    int tid = threadIdx.x;
    int lane = tid & 31, wid = tid >> 5;
    int wm = wid & 1, wn = wid >> 1;       // 2m x 4n warps, 64x64 each

    int NTX = N >> 8;                      // 256-col tiles
    int ntiles = (M >> 7) * NTX;           // 128-row tiles

    int m4 = lane >> 3, rin = lane & 7;
    int a_row = wm * 64 + ((m4 & 1) << 3) + rin;
    int a_kc  = (m4 >> 1) << 3;
    int b_row = wn * 64 + ((lane >> 4) << 3) + rin;
    int b_kc  = ((lane >> 3) & 1) << 3;

    const int NC = K / 32;

#define SETP(T, pA, pB, pC, pD, r0_, c0_) do {                               \
        int by_ = (T) / NTX, bx_ = (T) % NTX;                                \
        r0_ = by_ * 128; c0_ = bx_ * 256;                                    \
        pA = Ahi + (size_t)r0_ * K;  pB = Alo + (size_t)r0_ * K;             \
        pC = Bhi + (size_t)c0_ * K;  pD = Blo + (size_t)c0_ * K;             \
    } while (0)

    // 12 cp16 per thread per stage: A hi/lo 2 rounds each, B hi/lo 4 rounds
#define LOAD_STAGE(stg, kc, PA, PAl, PB, PBl) do {                           \
        uint32_t base_ = sb + (stg) * STAGE_B;                               \
        _Pragma("unroll")                                                    \
        for (int j_ = 0; j_ < 2; j_++) {                                     \
            int c_ = tid + 256 * j_;                                         \
            int r_ = c_ >> 2, cl_ = c_ & 3;                                  \
            cp16(base_ + (uint32_t)r_ * RS + cl_ * 16,                       \
                 PA  + (size_t)r_ * K + (kc) + cl_ * 8);                     \
            cp16(base_ + OFF_ALO + (uint32_t)r_ * RS + cl_ * 16,             \
                 PAl + (size_t)r_ * K + (kc) + cl_ * 8);                     \
        }                                                                    \
        _Pragma("unroll")                                                    \
        for (int j_ = 0; j_ < 4; j_++) {                                     \
            int c_ = tid + 256 * j_;                                         \
            int r_ = c_ >> 2, cl_ = c_ & 3;                                  \
            cp16(base_ + OFF_BHI + (uint32_t)r_ * RS + cl_ * 16,             \
                 PB  + (size_t)r_ * K + (kc) + cl_ * 8);                     \
            cp16(base_ + OFF_BLO + (uint32_t)r_ * RS + cl_ * 16,             \
                 PBl + (size_t)r_ * K + (kc) + cl_ * 8);                     \
        } } while (0)

    int t = blockIdx.x;
    if (t >= ntiles) return;
    const __nv_bfloat16 *pAh, *pAl, *pBh, *pBl;
    int row0, col0;
    SETP(t, pAh, pAl, pBh, pBl, row0, col0);
    LOAD_STAGE(0, 0, pAh, pAl, pBh, pBl);
    CP_COMMIT();

    while (1) {
        float acc[4][8][4];
        #pragma unroll
        for (int i = 0; i < 4; i++)
            #pragma unroll
            for (int j = 0; j < 8; j++)
                #pragma unroll
                for (int r = 0; r < 4; r++) acc[i][j][r] = 0.f;

        int tn = t + gridDim.x;
        const __nv_bfloat16 *nAh = 0, *nAl = 0, *nBh = 0, *nBl = 0;
        int nrow0 = 0, ncol0 = 0;

        for (int c = 0; c < NC; c++) {
            int st = c & 1;
            if (c + 1 < NC) {
                LOAD_STAGE(st ^ 1, (c + 1) * 32, pAh, pAl, pBh, pBl);
                CP_COMMIT();
                CP_WAIT(1);
            } else if (tn < ntiles) {
                SETP(tn, nAh, nAl, nBh, nBl, nrow0, ncol0);
                LOAD_STAGE(st ^ 1, 0, nAh, nAl, nBh, nBl);   // cross-tile prefetch
                CP_COMMIT();
                CP_WAIT(1);
            } else {
                CP_WAIT(0);
            }
            __syncthreads();

            uint32_t aB = sb + st * STAGE_B;
            #pragma unroll
            for (int ks = 0; ks < 2; ks++) {
                uint32_t af[4][4], bhf[8][2], blf[8][2];
                uint32_t adh[4];
                #pragma unroll
                for (int mi = 0; mi < 4; mi++)
                    adh[mi] = aB + (uint32_t)(a_row + mi * 16) * RS
                                 + (uint32_t)(ks * 16 + a_kc) * 2;
                uint32_t bd = aB + OFF_BHI + (uint32_t)b_row * RS
                                 + (uint32_t)(ks * 16 + b_kc) * 2;

                #pragma unroll
                for (int mi = 0; mi < 4; mi++)
                    LDSM4(af[mi][0], af[mi][1], af[mi][2], af[mi][3], adh[mi]);
                #pragma unroll
                for (int np = 0; np < 4; np++) {
                    uint32_t t0, t1, t2, t3;
                    LDSM4(t0, t1, t2, t3, bd + (uint32_t)(np * 16) * RS);
                    bhf[np * 2][0] = t0; bhf[np * 2][1] = t1;
                    bhf[np * 2 + 1][0] = t2; bhf[np * 2 + 1][1] = t3;
                }
                #pragma unroll
                for (int np = 0; np < 4; np++) {
                    uint32_t t0, t1, t2, t3;
                    LDSM4(t0, t1, t2, t3, bd + (OFF_BLO - OFF_BHI) + (uint32_t)(np * 16) * RS);
                    blf[np * 2][0] = t0; blf[np * 2][1] = t1;
                    blf[np * 2 + 1][0] = t2; blf[np * 2 + 1][1] = t3;
                }

                // pass 0: Ahi*Bhi
                #pragma unroll
                for (int mi = 0; mi < 4; mi++)
                    #pragma unroll
                    for (int ni = 0; ni < 8; ni++)
                        MMA16816(acc[mi][ni], af[mi], bhf[ni]);
                // pass 1: Ahi*Blo
                #pragma unroll
                for (int mi = 0; mi < 4; mi++)
                    #pragma unroll
                    for (int ni = 0; ni < 8; ni++)
                        MMA16816(acc[mi][ni], af[mi], blf[ni]);
                // load Alo into af, pass 2: Alo*Bhi
                #pragma unroll
                for (int mi = 0; mi < 4; mi++)
                    LDSM4(af[mi][0], af[mi][1], af[mi][2], af[mi][3], adh[mi] + OFF_ALO);
                #pragma unroll
                for (int mi = 0; mi < 4; mi++)
                    #pragma unroll
                    for (int ni = 0; ni < 8; ni++)
                        MMA16816(acc[mi][ni], af[mi], bhf[ni]);
            }
            __syncthreads();
        }

        // epilogue for tile t
        int g = lane >> 2, tg = lane & 3;
        #pragma unroll
        for (int mi = 0; mi < 4; mi++) {
            int row = row0 + wm * 64 + mi * 16 + g;
            #pragma unroll
            for (int ni = 0; ni < 8; ni++) {
                int col = col0 + wn * 64 + ni * 8 + tg * 2;
                float2 bb = *(const float2*)(bias + col);
                float v0x = acc[mi][ni][0] + bb.x, v0y = acc[mi][ni][1] + bb.y;
                float v1x = acc[mi][ni][2] + bb.x, v1y = acc[mi][ni][3] + bb.y;
                if (Chi) {
                    uint32_t lo0, lo1;
                    uint32_t hi0 = packpair(v0x, v0y, lo0);
                    uint32_t hi1 = packpair(v1x, v1y, lo1);
                    *(uint32_t*)(Chi + (size_t)row * N + col) = hi0;
                    *(uint32_t*)(Clo + (size_t)row * N + col) = lo0;
                    *(uint32_t*)(Chi + (size_t)(row + 8) * N + col) = hi1;
                    *(uint32_t*)(Clo + (size_t)(row + 8) * N + col) = lo1;
                } else {
                    float2 v0; v0.x = v0x; v0.y = v0y;
                    float2 v1; v1.x = v1x; v1.y = v1y;
                    *(float2*)(C + (size_t)row * N + col) = v0;
                    *(float2*)(C + (size_t)(row + 8) * N + col) = v1;
                }
            }
        }

        if (tn >= ntiles) break;
        t = tn;
        pAh = nAh; pAl = nAl; pBh = nBh; pBl = nBl;
        row0 = nrow0; col0 = ncol0;
    }
#undef LOAD_STAGE
#undef SETP
}

// ---------------------------------------------------------------------------
// Flash attention (causal) mma.sync bf16 hi/lo (verified R7/R14 structure —
// UNCHANGED; load-first prefetch protected by the trailing __syncthreads()).
// ---------------------------------------------------------------------------
#define RS2 144
#define TILE_KV 9216
#define STAGE_KV 36864
#define QOFF 73728
#define ATT_SMEM 110592

__global__ __launch_bounds__(256, 1)
void flash_attn_mma(const __nv_bfloat16* __restrict__ qkvhi,
                    const __nv_bfloat16* __restrict__ qkvlo,
                    __nv_bfloat16* __restrict__ ahi,
                    __nv_bfloat16* __restrict__ alo)
{
    extern __shared__ char smem[];
    const uint32_t sb = smem_u32(smem);
    int tid = threadIdx.x, lane = tid & 31, w = tid >> 5;
    int h = blockIdx.y, b = blockIdx.z;
    int q0 = (int)(gridDim.x - 1 - blockIdx.x) * 128;

    const __nv_bfloat16* qh_g = qkvhi + (size_t)b * SEQ * QKV_N + h * 192;
    const __nv_bfloat16* ql_g = qkvlo + (size_t)b * SEQ * QKV_N + h * 192;
    const __nv_bfloat16* kvsrc[4] = {qh_g + 64, ql_g + 64, qh_g + 128, ql_g + 128};

    #pragma unroll
    for (int i = 0; i < 8; i++) {
        int part = i >> 2;
        int rem = tid + 256 * (i & 3);
        int rw = rem >> 3, cc = rem & 7;
        const __nv_bfloat16* src = (part ? ql_g : qh_g) + (size_t)(q0 + rw) * QKV_N + cc * 8;
        cp16(sb + QOFF + part * 18432 + (uint32_t)rw * RS2 + cc * 16, src);
    }
    CP_COMMIT();

#define LOAD_KV(stg, kk) do {                                                  \
        _Pragma("unroll")                                                      \
        for (int i_ = 0; i_ < 8; i_++) {                                       \
            int sub_ = i_ >> 1;                                                \
            int rem_ = tid + 256 * (i_ & 1);                                   \
            int rw_ = rem_ >> 3, cc_ = rem_ & 7;                               \
            const __nv_bfloat16* src_ =                                        \
                kvsrc[sub_] + (size_t)((kk) + rw_) * QKV_N + cc_ * 8;          \
            cp16(sb + (stg) * STAGE_KV + sub_ * TILE_KV +                      \
                 (uint32_t)rw_ * RS2 + cc_ * 16, src_);                        \
        } } while (0)

    LOAD_KV(0, 0);
    CP_COMMIT();
    CP_WAIT(1);
    __syncthreads();

    uint32_t qhf[4][4], qlf[4][4];
    {
        int ar = 16 * w + (((lane >> 3) & 1) << 3) + (lane & 7);
        int akc = (lane >> 4) << 3;
        #pragma unroll
        for (int ks = 0; ks < 4; ks++) {
            uint32_t ad = sb + QOFF + (uint32_t)ar * RS2 + (uint32_t)(ks * 16 + akc) * 2;
            LDSM4(qhf[ks][0], qhf[ks][1], qhf[ks][2], qhf[ks][3], ad);
            LDSM4(qlf[ks][0], qlf[ks][1], qlf[ks][2], qlf[ks][3], ad + 18432);
        }
    }

    int g = lane >> 2, tg = lane & 3;
    int qr0 = q0 + 16 * w + g, qr1 = qr0 + 8;
    int qmax = q0 + 16 * w + 15;

    float o[8][4];
    #pragma unroll
    for (int nt = 0; nt < 8; nt++)
        #pragma unroll
        for (int i = 0; i < 4; i++) o[nt][i] = 0.f;
    float m0 = -1e30f, m1 = -1e30f, l0 = 0.f, l1 = 0.f;

    int ntile = q0 / 64 + 2;
    int krow = (((lane >> 4)) << 3) + (lane & 7);
    int kkc  = ((lane >> 3) & 1) << 3;
    int vrow_b = (((lane >> 3) & 1) << 3) + (lane & 7);
    int vcol_b = (lane >> 4) << 3;

    for (int t = 0; t < ntile; t++) {
        int k0 = t * 64;
        int buf = t & 1;
        if (t + 1 < ntile) {
            LOAD_KV(buf ^ 1, (t + 1) * 64);
            CP_COMMIT();
            CP_WAIT(1);
        } else {
            CP_WAIT(0);
        }
        __syncthreads();

        if (k0 <= qmax) {
            uint32_t kb = sb + buf * STAGE_KV;
            float s[8][4];
            #pragma unroll
            for (int nt = 0; nt < 8; nt++)
                #pragma unroll
                for (int i = 0; i < 4; i++) s[nt][i] = 0.f;

            #pragma unroll
            for (int ks = 0; ks < 4; ks++) {
                uint32_t khf[8][2], klf[8][2];
                #pragma unroll
                for (int n16 = 0; n16 < 4; n16++) {
                    uint32_t ad = kb + (uint32_t)(n16 * 16 + krow) * RS2
                                     + (uint32_t)(ks * 16 + kkc) * 2;
                    uint32_t t0, t1, t2, t3;
                    LDSM4(t0, t1, t2, t3, ad);
                    khf[n16 * 2][0] = t0; khf[n16 * 2][1] = t1;
                    khf[n16 * 2 + 1][0] = t2; khf[n16 * 2 + 1][1] = t3;
                    LDSM4(t0, t1, t2, t3, ad + TILE_KV);
                    klf[n16 * 2][0] = t0; klf[n16 * 2][1] = t1;
                    klf[n16 * 2 + 1][0] = t2; klf[n16 * 2 + 1][1] = t3;
                }
                #pragma unroll
                for (int nt = 0; nt < 8; nt++) MMA16816(s[nt], qhf[ks], khf[nt]);
                #pragma unroll
                for (int nt = 0; nt < 8; nt++) MMA16816(s[nt], qlf[ks], khf[nt]);
                #pragma unroll
                for (int nt = 0; nt < 8; nt++) MMA16816(s[nt], qhf[ks], klf[nt]);
            }

            #pragma unroll
            for (int nt = 0; nt < 8; nt++)
                #pragma unroll
                for (int i = 0; i < 4; i++) s[nt][i] *= 0.125f;
            if (k0 + 63 > q0 + 16 * w) {
                #pragma unroll
                for (int nt = 0; nt < 8; nt++) {
                    int c = k0 + nt * 8 + 2 * tg;
                    if (c     > qr0) s[nt][0] = -1e30f;
                    if (c + 1 > qr0) s[nt][1] = -1e30f;
                    if (c     > qr1) s[nt][2] = -1e30f;
                    if (c + 1 > qr1) s[nt][3] = -1e30f;
                }
            }

            float rm0 = -1e30f, rm1 = -1e30f;
            #pragma unroll
            for (int nt = 0; nt < 8; nt++) {
                rm0 = fmaxf(rm0, fmaxf(s[nt][0], s[nt][1]));
                rm1 = fmaxf(rm1, fmaxf(s[nt][2], s[nt][3]));
            }
            rm0 = fmaxf(rm0, __shfl_xor_sync(0xffffffffu, rm0, 1));
            rm0 = fmaxf(rm0, __shfl_xor_sync(0xffffffffu, rm0, 2));
            rm1 = fmaxf(rm1, __shfl_xor_sync(0xffffffffu, rm1, 1));
            rm1 = fmaxf(rm1, __shfl_xor_sync(0xffffffffu, rm1, 2));
            float mn0 = fmaxf(m0, rm0), mn1 = fmaxf(m1, rm1);
            float al0 = __expf(m0 - mn0), al1 = __expf(m1 - mn1);
            m0 = mn0; m1 = mn1;
            float rs0 = 0.f, rs1 = 0.f;
            #pragma unroll
            for (int nt = 0; nt < 8; nt++) {
                s[nt][0] = __expf(s[nt][0] - mn0);
                s[nt][1] = __expf(s[nt][1] - mn0);
                s[nt][2] = __expf(s[nt][2] - mn1);
                s[nt][3] = __expf(s[nt][3] - mn1);
                rs0 += s[nt][0] + s[nt][1];
                rs1 += s[nt][2] + s[nt][3];
            }
            rs0 += __shfl_xor_sync(0xffffffffu, rs0, 1);
            rs0 += __shfl_xor_sync(0xffffffffu, rs0, 2);
            rs1 += __shfl_xor_sync(0xffffffffu, rs1, 1);
            rs1 += __shfl_xor_sync(0xffffffffu, rs1, 2);
            l0 = l0 * al0 + rs0;
            l1 = l1 * al1 + rs1;
            #pragma unroll
            for (int nt = 0; nt < 8; nt++) {
                o[nt][0] *= al0; o[nt][1] *= al0;
                o[nt][2] *= al1; o[nt][3] *= al1;
            }

            uint32_t phi[4][4], plo[4][4];
            #pragma unroll
            for (int ks = 0; ks < 4; ks++) {
                phi[ks][0] = packpair(s[2 * ks][0],     s[2 * ks][1],     plo[ks][0]);
                phi[ks][1] = packpair(s[2 * ks][2],     s[2 * ks][3],     plo[ks][1]);
                phi[ks][2] = packpair(s[2 * ks + 1][0], s[2 * ks + 1][1], plo[ks][2]);
                phi[ks][3] = packpair(s[2 * ks + 1][2], s[2 * ks + 1][3], plo[ks][3]);
            }

            uint32_t vb = kb + 2 * TILE_KV;
            #pragma unroll
            for (int ks = 0; ks < 4; ks++) {
                uint32_t vhf[8][2], vlf[8][2];
                #pragma unroll
                for (int n16 = 0; n16 < 4; n16++) {
                    uint32_t ad = vb + (uint32_t)(ks * 16 + vrow_b) * RS2
                                     + (uint32_t)(n16 * 16 + vcol_b) * 2;
                    uint32_t t0, t1, t2, t3;
                    LDSM4T(t0, t1, t2, t3, ad);
                    vhf[n16 * 2][0] = t0; vhf[n16 * 2][1] = t1;
                    vhf[n16 * 2 + 1][0] = t2; vhf[n16 * 2 + 1][1] = t3;
                    LDSM4T(t0, t1, t2, t3, ad + TILE_KV);
                    vlf[n16 * 2][0] = t0; vlf[n16 * 2][1] = t1;
                    vlf[n16 * 2 + 1][0] = t2; vlf[n16 * 2 + 1][1] = t3;
                }
                #pragma unroll
                for (int nt = 0; nt < 8; nt++) MMA16816(o[nt], phi[ks], vhf[nt]);
                #pragma unroll
                for (int nt = 0; nt < 8; nt++) MMA16816(o[nt], plo[ks], vhf[nt]);
                #pragma unroll
                for (int nt = 0; nt < 8; nt++) MMA16816(o[nt], phi[ks], vlf[nt]);
            }
        }
        __syncthreads();
    }
#undef LOAD_KV

    float inv0 = 1.f / l0, inv1 = 1.f / l1;
    size_t base0 = ((size_t)(b * NUM_HEAD + h) * SEQ + qr0) * HEAD_DIM;
    size_t base1 = ((size_t)(b * NUM_HEAD + h) * SEQ + qr1) * HEAD_DIM;
    #pragma unroll
    for (int nt = 0; nt < 8; nt++) {
        int col = nt * 8 + 2 * tg;
        uint32_t lo0, lo1;
        uint32_t hi0 = packpair(o[nt][0] * inv0, o[nt][1] * inv0, lo0);
        uint32_t hi1 = packpair(o[nt][2] * inv1, o[nt][3] * inv1, lo1);
        *(uint32_t*)(ahi + base0 + col) = hi0;
        *(uint32_t*)(alo + base0 + col) = lo0;
        *(uint32_t*)(ahi + base1 + col) = hi1;
        *(uint32_t*)(alo + base1 + col) = lo1;
    }
}

// ---------------------------------------------------------------------------
extern "C" void kernel_launch(void* const* d_in, const int* in_sizes, int n_in,
                              void* d_out, int out_size)
{
    const float* x     = (const float*)d_in[0];
    const float* w_qkv = (const float*)d_in[1];
    const float* b_qkv = (const float*)d_in[2];
    const float* w_out = (const float*)d_in[3];
    const float* b_out = (const float*)d_in[4];
    float* out = (float*)d_out;

    __nv_bfloat16 *qkvhi, *qkvlo, *xhi, *xlo, *wqhi, *wqlo, *wohi, *wolo, *ahi, *alo;
    cudaGetSymbolAddress((void**)&qkvhi, g_qkvhi);
    cudaGetSymbolAddress((void**)&qkvlo, g_qkvlo);
    cudaGetSymbolAddress((void**)&xhi, g_xhi);
    cudaGetSymbolAddress((void**)&xlo, g_xlo);
    cudaGetSymbolAddress((void**)&wqhi, g_wqT_hi);
    cudaGetSymbolAddress((void**)&wqlo, g_wqT_lo);
    cudaGetSymbolAddress((void**)&wohi, g_woT_hi);
    cudaGetSymbolAddress((void**)&wolo, g_woT_lo);
    cudaGetSymbolAddress((void**)&ahi, g_ahi);
    cudaGetSymbolAddress((void**)&alo, g_alo);

    cudaFuncSetAttribute(gemm_mma, cudaFuncAttributeMaxDynamicSharedMemorySize, GEMM_SMEM);
    cudaFuncSetAttribute(flash_attn_mma, cudaFuncAttributeMaxDynamicSharedMemorySize, ATT_SMEM);

    // 0) decompose x and weights
    decomp_kernel<<<MROWS * D_MODEL / 1024, 256>>>(x, xhi, xlo, MROWS * D_MODEL);
    transdecomp_kernel<<<dim3(QKV_N / 32, D_MODEL / 32), dim3(32, 8)>>>(w_qkv, wqhi, wqlo, D_MODEL, QKV_N);
    transdecomp_kernel<<<dim3(D_MODEL / 32, D_MODEL / 32), dim3(32, 8)>>>(w_out, wohi, wolo, D_MODEL, D_MODEL);

    // 1) QKV projection -> hi/lo bf16 (persistent grid, 128x256 tiles)
    {
        int ntiles = (MROWS / 128) * (QKV_N / 256);   // 384
        int grid = ntiles < 148 ? ntiles : 148;
        gemm_mma<<<grid, 256, GEMM_SMEM>>>(
            xhi, xlo, wqhi, wqlo, b_qkv, nullptr, qkvhi, qkvlo, MROWS, QKV_N, D_MODEL);
    }

    // 2) causal flash attention (tensor cores) -> ahi/alo
    flash_attn_mma<<<dim3(SEQ / 128, NUM_HEAD, BATCH), 256, ATT_SMEM>>>(
        qkvhi, qkvlo, ahi, alo);

    // 3) output projection -> fp32 out
    {
        int ntiles = (MROWS / 128) * (D_MODEL / 256); // 128
        int grid = ntiles < 148 ? ntiles : 148;
        gemm_mma<<<grid, 256, GEMM_SMEM>>>(
            ahi, alo, wohi, wolo, b_out, out, nullptr, nullptr, MROWS, D_MODEL, D_MODEL);
    }
}

// round 17
// speedup vs baseline: 1.1337x; 1.1337x over previous
#include <cuda_runtime.h>
#include <cuda_bf16.h>
#include <stdint.h>
#include <math.h>

#define NUM_HEAD 16
#define D_MODEL 1024
#define HEAD_DIM 64
#define BATCH 2
#define SEQ 2048
#define MROWS (BATCH * SEQ)          // 4096
#define QKV_N (3 * D_MODEL)          // 3072

// ---------------- scratch (device globals: allocation-guard safe) ----------
__device__ __nv_bfloat16 g_qkvhi[(size_t)MROWS * QKV_N];
__device__ __nv_bfloat16 g_qkvlo[(size_t)MROWS * QKV_N];
__device__ __nv_bfloat16 g_xhi[(size_t)MROWS * D_MODEL];
__device__ __nv_bfloat16 g_xlo[(size_t)MROWS * D_MODEL];
__device__ __nv_bfloat16 g_wqT_hi[(size_t)QKV_N * D_MODEL];
__device__ __nv_bfloat16 g_wqT_lo[(size_t)QKV_N * D_MODEL];
__device__ __nv_bfloat16 g_woT_hi[(size_t)D_MODEL * D_MODEL];
__device__ __nv_bfloat16 g_woT_lo[(size_t)D_MODEL * D_MODEL];
__device__ __nv_bfloat16 g_ahi[(size_t)MROWS * D_MODEL];
__device__ __nv_bfloat16 g_alo[(size_t)MROWS * D_MODEL];

// ---------------- PTX helpers ----------------------------------------------
__device__ __forceinline__ uint32_t smem_u32(const void* p) {
    uint32_t a;
    asm("{ .reg .u64 t; cvta.to.shared.u64 t, %1; cvt.u32.u64 %0, t; }" : "=r"(a) : "l"(p));
    return a;
}
__device__ __forceinline__ void cp16(uint32_t dst, const void* src) {
    asm volatile("cp.async.cg.shared.global [%0], [%1], 16;" :: "r"(dst), "l"(src) : "memory");
}
#define CP_COMMIT() asm volatile("cp.async.commit_group;" ::: "memory")
#define CP_WAIT(n)  asm volatile("cp.async.wait_group %0;" :: "n"(n) : "memory")

#define LDSM4(r0, r1, r2, r3, addr) \
    asm volatile("ldmatrix.sync.aligned.m8n8.x4.shared.b16 {%0,%1,%2,%3}, [%4];" \
                 : "=r"(r0), "=r"(r1), "=r"(r2), "=r"(r3) : "r"(addr))
#define LDSM4T(r0, r1, r2, r3, addr) \
    asm volatile("ldmatrix.sync.aligned.m8n8.x4.trans.shared.b16 {%0,%1,%2,%3}, [%4];" \
                 : "=r"(r0), "=r"(r1), "=r"(r2), "=r"(r3) : "r"(addr))

#define MMA16816(d, a, b) \
    asm volatile("mma.sync.aligned.m16n8k16.row.col.f32.bf16.bf16.f32 " \
                 "{%0,%1,%2,%3},{%4,%5,%6,%7},{%8,%9},{%0,%1,%2,%3};" \
                 : "+f"((d)[0]), "+f"((d)[1]), "+f"((d)[2]), "+f"((d)[3]) \
                 : "r"((a)[0]), "r"((a)[1]), "r"((a)[2]), "r"((a)[3]), \
                   "r"((b)[0]), "r"((b)[1]))

__device__ __forceinline__ uint32_t packpair(float x, float y, uint32_t& lo) {
    __nv_bfloat16 hx = __float2bfloat16(x), hy = __float2bfloat16(y);
    __nv_bfloat162 h; h.x = hx; h.y = hy;
    __nv_bfloat162 l;
    l.x = __float2bfloat16(x - __bfloat162float(hx));
    l.y = __float2bfloat16(y - __bfloat162float(hy));
    lo = *(uint32_t*)&l;
    return *(uint32_t*)&h;
}

// ---------------------------------------------------------------------------
// Fused prep: one launch covering
//   blocks [0, 4096)            : decomp x            (4M elems, 4/thread)
//   blocks [4096, 4096+3072)    : transdecomp w_qkv   (96 x 32 virtual grid)
//   blocks [7168, 8192)         : transdecomp w_out   (32 x 32 virtual grid)
// Per-element math identical to the previous separate kernels.
// ---------------------------------------------------------------------------
__device__ __forceinline__ void transdecomp_body(
    const float* __restrict__ W, __nv_bfloat16* __restrict__ Thi,
    __nv_bfloat16* __restrict__ Tlo, int K, int N,
    int n0, int k0, int tx, int ty, float (*tile)[33])
{
    #pragma unroll
    for (int i = 0; i < 4; i++)
        tile[ty + i * 8][tx] =
            W[(size_t)(k0 + ty + i * 8) * N + n0 + tx];
    __syncthreads();
    #pragma unroll
    for (int i = 0; i < 4; i++) {
        int n = n0 + ty + i * 8;
        int k = k0 + tx;
        float v = tile[tx][ty + i * 8];
        __nv_bfloat16 h = __float2bfloat16(v);
        Thi[(size_t)n * K + k] = h;
        Tlo[(size_t)n * K + k] = __float2bfloat16(v - __bfloat162float(h));
    }
}

__global__ void prep_kernel(const float* __restrict__ x,
                            __nv_bfloat16* __restrict__ xhi, __nv_bfloat16* __restrict__ xlo,
                            const float* __restrict__ wq,
                            __nv_bfloat16* __restrict__ wqhi, __nv_bfloat16* __restrict__ wqlo,
                            const float* __restrict__ wo,
                            __nv_bfloat16* __restrict__ wohi, __nv_bfloat16* __restrict__ wolo)
{
    __shared__ float tile[32][33];
    int bid = blockIdx.x;
    int tid = threadIdx.x;

    if (bid < 4096) {
        // ---- decomp x ----
        int i = (bid * 256 + tid) * 4;           // covers 4096*256*4 = 4,194,304 exactly
        float4 v = *(const float4*)(x + i);
        uint32_t l0, l1;
        uint32_t h0 = packpair(v.x, v.y, l0);
        uint32_t h1 = packpair(v.z, v.w, l1);
        *(uint32_t*)(xhi + i) = h0; *(uint32_t*)(xhi + i + 2) = h1;
        *(uint32_t*)(xlo + i) = l0; *(uint32_t*)(xlo + i + 2) = l1;
    } else if (bid < 4096 + 3072) {
        // ---- transdecomp w_qkv: virtual grid (96, 32) ----
        int vb = bid - 4096;
        int bx = vb % (QKV_N / 32);              // 96
        int by = vb / (QKV_N / 32);              // 32
        transdecomp_body(wq, wqhi, wqlo, D_MODEL, QKV_N,
                         bx * 32, by * 32, tid & 31, tid >> 5, tile);
    } else {
        // ---- transdecomp w_out: virtual grid (32, 32) ----
        int vb = bid - 4096 - 3072;
        int bx = vb % (D_MODEL / 32);            // 32
        int by = vb / (D_MODEL / 32);            // 32
        transdecomp_body(wo, wohi, wolo, D_MODEL, D_MODEL,
                         bx * 32, by * 32, tid & 31, tid >> 5, tile);
    }
}

// ---------------------------------------------------------------------------
// Fused decomp for attention output (unchanged path: attention writes hi/lo
// directly, so no decomp needed there).
// ---------------------------------------------------------------------------

// ---------------------------------------------------------------------------
// Persistent mma.sync bf16 hi/lo GEMM: C = A[M,K]@B[N,K]^T + bias.
// 128 threads (4 warps 2m x 2n), warp tile 64x64, acc[4][8][4].
// Verified R7/R14 load-first double-barrier chunk loop: the trailing
// __syncthreads() protects the buffer the next chunk's prefetch overwrites.
// ---------------------------------------------------------------------------
#define RS 80
#define TILE_B 10240          // 128 rows * 80B
#define STAGE_B 40960         // Ahi,Alo,Bhi,Blo
#define GEMM_SMEM 81920       // 2 stages

__global__ __launch_bounds__(128, 2)
void gemm_mma(const __nv_bfloat16* __restrict__ Ahi, const __nv_bfloat16* __restrict__ Alo,
              const __nv_bfloat16* __restrict__ Bhi, const __nv_bfloat16* __restrict__ Blo,
              const float* __restrict__ bias, float* __restrict__ C,
              __nv_bfloat16* __restrict__ Chi, __nv_bfloat16* __restrict__ Clo,
              int M, int N, int K)
{
    extern __shared__ char smem[];
    const uint32_t sb = smem_u32(smem);
    int tid = threadIdx.x;
    int lane = tid & 31, wid = tid >> 5;
    int wm = wid & 1, wn = wid >> 1;       // 2m x 2n warps, 64x64 each

    int NTX = N >> 7;
    int ntiles = (M >> 7) * NTX;

    int m4 = lane >> 3, rin = lane & 7;
    int a_row = wm * 64 + ((m4 & 1) << 3) + rin;
    int a_kc  = (m4 >> 1) << 3;
    int b_row = wn * 64 + ((lane >> 4) << 3) + rin;
    int b_kc  = ((lane >> 3) & 1) << 3;

    const int NC = K / 32;

#define SETP(T, pA, pB, pC, pD, r0_, c0_) do {                               \
        int by_ = (T) / NTX, bx_ = (T) % NTX;                                \
        r0_ = by_ * 128; c0_ = bx_ * 128;                                    \
        pA = Ahi + (size_t)r0_ * K;  pB = Alo + (size_t)r0_ * K;             \
        pC = Bhi + (size_t)c0_ * K;  pD = Blo + (size_t)c0_ * K;             \
    } while (0)

#define LOAD_STAGE(stg, kc, P0, P1, P2, P3) do {                             \
        const __nv_bfloat16* PP_[4] = {P0, P1, P2, P3};                      \
        _Pragma("unroll")                                                    \
        for (int i_ = 0; i_ < 16; i_++) {                                    \
            int tl_ = i_ >> 2;                                               \
            int ci_ = (tid + 128 * i_) & 511;                                \
            int rw_ = ci_ >> 2, cl_ = ci_ & 3;                               \
            cp16(sb + (stg) * STAGE_B + tl_ * TILE_B                         \
                    + (uint32_t)rw_ * RS + cl_ * 16,                         \
                 PP_[tl_] + (size_t)rw_ * K + (kc) + cl_ * 8);               \
        } } while (0)

    int t = blockIdx.x;
    if (t >= ntiles) return;
    const __nv_bfloat16 *pAh, *pAl, *pBh, *pBl;
    int row0, col0;
    SETP(t, pAh, pAl, pBh, pBl, row0, col0);
    LOAD_STAGE(0, 0, pAh, pAl, pBh, pBl);
    CP_COMMIT();

    while (1) {
        float acc[4][8][4];
        #pragma unroll
        for (int i = 0; i < 4; i++)
            #pragma unroll
            for (int j = 0; j < 8; j++)
                #pragma unroll
                for (int r = 0; r < 4; r++) acc[i][j][r] = 0.f;

        int tn = t + gridDim.x;
        const __nv_bfloat16 *nAh = 0, *nAl = 0, *nBh = 0, *nBl = 0;
        int nrow0 = 0, ncol0 = 0;

        for (int c = 0; c < NC; c++) {
            int st = c & 1;
            if (c + 1 < NC) {
                LOAD_STAGE(st ^ 1, (c + 1) * 32, pAh, pAl, pBh, pBl);
                CP_COMMIT();
                CP_WAIT(1);
            } else if (tn < ntiles) {
                SETP(tn, nAh, nAl, nBh, nBl, nrow0, ncol0);
                LOAD_STAGE(st ^ 1, 0, nAh, nAl, nBh, nBl);   // cross-tile prefetch
                CP_COMMIT();
                CP_WAIT(1);
            } else {
                CP_WAIT(0);
            }
            __syncthreads();

            uint32_t aB = sb + st * STAGE_B;
            #pragma unroll
            for (int ks = 0; ks < 2; ks++) {
                uint32_t af[4][4], bhf[8][2], blf[8][2];
                uint32_t adh[4];
                #pragma unroll
                for (int mi = 0; mi < 4; mi++)
                    adh[mi] = aB + (uint32_t)(a_row + mi * 16) * RS
                                 + (uint32_t)(ks * 16 + a_kc) * 2;
                uint32_t bd = aB + 2 * TILE_B + (uint32_t)b_row * RS
                                 + (uint32_t)(ks * 16 + b_kc) * 2;

                #pragma unroll
                for (int mi = 0; mi < 4; mi++)
                    LDSM4(af[mi][0], af[mi][1], af[mi][2], af[mi][3], adh[mi]);
                #pragma unroll
                for (int np = 0; np < 4; np++) {
                    uint32_t t0, t1, t2, t3;
                    LDSM4(t0, t1, t2, t3, bd + (uint32_t)(np * 16) * RS);
                    bhf[np * 2][0] = t0; bhf[np * 2][1] = t1;
                    bhf[np * 2 + 1][0] = t2; bhf[np * 2 + 1][1] = t3;
                }
                #pragma unroll
                for (int np = 0; np < 4; np++) {
                    uint32_t t0, t1, t2, t3;
                    LDSM4(t0, t1, t2, t3, bd + TILE_B + (uint32_t)(np * 16) * RS);
                    blf[np * 2][0] = t0; blf[np * 2][1] = t1;
                    blf[np * 2 + 1][0] = t2; blf[np * 2 + 1][1] = t3;
                }

                // pass 0: Ahi*Bhi
                #pragma unroll
                for (int mi = 0; mi < 4; mi++)
                    #pragma unroll
                    for (int ni = 0; ni < 8; ni++)
                        MMA16816(acc[mi][ni], af[mi], bhf[ni]);
                // pass 1: Ahi*Blo
                #pragma unroll
                for (int mi = 0; mi < 4; mi++)
                    #pragma unroll
                    for (int ni = 0; ni < 8; ni++)
                        MMA16816(acc[mi][ni], af[mi], blf[ni]);
                // load Alo into af, pass 2: Alo*Bhi
                #pragma unroll
                for (int mi = 0; mi < 4; mi++)
                    LDSM4(af[mi][0], af[mi][1], af[mi][2], af[mi][3], adh[mi] + TILE_B);
                #pragma unroll
                for (int mi = 0; mi < 4; mi++)
                    #pragma unroll
                    for (int ni = 0; ni < 8; ni++)
                        MMA16816(acc[mi][ni], af[mi], bhf[ni]);
            }
            __syncthreads();
        }

        // epilogue for tile t
        int g = lane >> 2, tg = lane & 3;
        #pragma unroll
        for (int mi = 0; mi < 4; mi++) {
            int row = row0 + wm * 64 + mi * 16 + g;
            #pragma unroll
            for (int ni = 0; ni < 8; ni++) {
                int col = col0 + wn * 64 + ni * 8 + tg * 2;
                float2 bb = *(const float2*)(bias + col);
                float v0x = acc[mi][ni][0] + bb.x, v0y = acc[mi][ni][1] + bb.y;
                float v1x = acc[mi][ni][2] + bb.x, v1y = acc[mi][ni][3] + bb.y;
                if (Chi) {
                    uint32_t lo0, lo1;
                    uint32_t hi0 = packpair(v0x, v0y, lo0);
                    uint32_t hi1 = packpair(v1x, v1y, lo1);
                    *(uint32_t*)(Chi + (size_t)row * N + col) = hi0;
                    *(uint32_t*)(Clo + (size_t)row * N + col) = lo0;
                    *(uint32_t*)(Chi + (size_t)(row + 8) * N + col) = hi1;
                    *(uint32_t*)(Clo + (size_t)(row + 8) * N + col) = lo1;
                } else {
                    float2 v0; v0.x = v0x; v0.y = v0y;
                    float2 v1; v1.x = v1x; v1.y = v1y;
                    *(float2*)(C + (size_t)row * N + col) = v0;
                    *(float2*)(C + (size_t)(row + 8) * N + col) = v1;
                }
            }
        }

        if (tn >= ntiles) break;
        t = tn;
        pAh = nAh; pAl = nAl; pBh = nBh; pBl = nBl;
        row0 = nrow0; col0 = ncol0;
    }
#undef LOAD_STAGE
#undef SETP
}

// ---------------------------------------------------------------------------
// Flash attention (causal) mma.sync bf16 hi/lo (verified R7/R14 structure —
// UNCHANGED; load-first prefetch protected by the trailing __syncthreads()).
// ---------------------------------------------------------------------------
#define RS2 144
#define TILE_KV 9216
#define STAGE_KV 36864
#define QOFF 73728
#define ATT_SMEM 110592

__global__ __launch_bounds__(256, 1)
void flash_attn_mma(const __nv_bfloat16* __restrict__ qkvhi,
                    const __nv_bfloat16* __restrict__ qkvlo,
                    __nv_bfloat16* __restrict__ ahi,
                    __nv_bfloat16* __restrict__ alo)
{
    extern __shared__ char smem[];
    const uint32_t sb = smem_u32(smem);
    int tid = threadIdx.x, lane = tid & 31, w = tid >> 5;
    int h = blockIdx.y, b = blockIdx.z;
    int q0 = (int)(gridDim.x - 1 - blockIdx.x) * 128;

    const __nv_bfloat16* qh_g = qkvhi + (size_t)b * SEQ * QKV_N + h * 192;
    const __nv_bfloat16* ql_g = qkvlo + (size_t)b * SEQ * QKV_N + h * 192;
    const __nv_bfloat16* kvsrc[4] = {qh_g + 64, ql_g + 64, qh_g + 128, ql_g + 128};

    #pragma unroll
    for (int i = 0; i < 8; i++) {
        int part = i >> 2;
        int rem = tid + 256 * (i & 3);
        int rw = rem >> 3, cc = rem & 7;
        const __nv_bfloat16* src = (part ? ql_g : qh_g) + (size_t)(q0 + rw) * QKV_N + cc * 8;
        cp16(sb + QOFF + part * 18432 + (uint32_t)rw * RS2 + cc * 16, src);
    }
    CP_COMMIT();

#define LOAD_KV(stg, kk) do {                                                  \
        _Pragma("unroll")                                                      \
        for (int i_ = 0; i_ < 8; i_++) {                                       \
            int sub_ = i_ >> 1;                                                \
            int rem_ = tid + 256 * (i_ & 1);                                   \
            int rw_ = rem_ >> 3, cc_ = rem_ & 7;                               \
            const __nv_bfloat16* src_ =                                        \
                kvsrc[sub_] + (size_t)((kk) + rw_) * QKV_N + cc_ * 8;          \
            cp16(sb + (stg) * STAGE_KV + sub_ * TILE_KV +                      \
                 (uint32_t)rw_ * RS2 + cc_ * 16, src_);                        \
        } } while (0)

    LOAD_KV(0, 0);
    CP_COMMIT();
    CP_WAIT(1);
    __syncthreads();

    uint32_t qhf[4][4], qlf[4][4];
    {
        int ar = 16 * w + (((lane >> 3) & 1) << 3) + (lane & 7);
        int akc = (lane >> 4) << 3;
        #pragma unroll
        for (int ks = 0; ks < 4; ks++) {
            uint32_t ad = sb + QOFF + (uint32_t)ar * RS2 + (uint32_t)(ks * 16 + akc) * 2;
            LDSM4(qhf[ks][0], qhf[ks][1], qhf[ks][2], qhf[ks][3], ad);
            LDSM4(qlf[ks][0], qlf[ks][1], qlf[ks][2], qlf[ks][3], ad + 18432);
        }
    }

    int g = lane >> 2, tg = lane & 3;
    int qr0 = q0 + 16 * w + g, qr1 = qr0 + 8;
    int qmax = q0 + 16 * w + 15;

    float o[8][4];
    #pragma unroll
    for (int nt = 0; nt < 8; nt++)
        #pragma unroll
        for (int i = 0; i < 4; i++) o[nt][i] = 0.f;
    float m0 = -1e30f, m1 = -1e30f, l0 = 0.f, l1 = 0.f;

    int ntile = q0 / 64 + 2;
    int krow = (((lane >> 4)) << 3) + (lane & 7);
    int kkc  = ((lane >> 3) & 1) << 3;
    int vrow_b = (((lane >> 3) & 1) << 3) + (lane & 7);
    int vcol_b = (lane >> 4) << 3;

    for (int t = 0; t < ntile; t++) {
        int k0 = t * 64;
        int buf = t & 1;
        if (t + 1 < ntile) {
            LOAD_KV(buf ^ 1, (t + 1) * 64);
            CP_COMMIT();
            CP_WAIT(1);
        } else {
            CP_WAIT(0);
        }
        __syncthreads();

        if (k0 <= qmax) {
            uint32_t kb = sb + buf * STAGE_KV;
            float s[8][4];
            #pragma unroll
            for (int nt = 0; nt < 8; nt++)
                #pragma unroll
                for (int i = 0; i < 4; i++) s[nt][i] = 0.f;

            #pragma unroll
            for (int ks = 0; ks < 4; ks++) {
                uint32_t khf[8][2], klf[8][2];
                #pragma unroll
                for (int n16 = 0; n16 < 4; n16++) {
                    uint32_t ad = kb + (uint32_t)(n16 * 16 + krow) * RS2
                                     + (uint32_t)(ks * 16 + kkc) * 2;
                    uint32_t t0, t1, t2, t3;
                    LDSM4(t0, t1, t2, t3, ad);
                    khf[n16 * 2][0] = t0; khf[n16 * 2][1] = t1;
                    khf[n16 * 2 + 1][0] = t2; khf[n16 * 2 + 1][1] = t3;
                    LDSM4(t0, t1, t2, t3, ad + TILE_KV);
                    klf[n16 * 2][0] = t0; klf[n16 * 2][1] = t1;
                    klf[n16 * 2 + 1][0] = t2; klf[n16 * 2 + 1][1] = t3;
                }
                #pragma unroll
                for (int nt = 0; nt < 8; nt++) MMA16816(s[nt], qhf[ks], khf[nt]);
                #pragma unroll
                for (int nt = 0; nt < 8; nt++) MMA16816(s[nt], qlf[ks], khf[nt]);
                #pragma unroll
                for (int nt = 0; nt < 8; nt++) MMA16816(s[nt], qhf[ks], klf[nt]);
            }

            #pragma unroll
            for (int nt = 0; nt < 8; nt++)
                #pragma unroll
                for (int i = 0; i < 4; i++) s[nt][i] *= 0.125f;
            if (k0 + 63 > q0 + 16 * w) {
                #pragma unroll
                for (int nt = 0; nt < 8; nt++) {
                    int c = k0 + nt * 8 + 2 * tg;
                    if (c     > qr0) s[nt][0] = -1e30f;
                    if (c + 1 > qr0) s[nt][1] = -1e30f;
                    if (c     > qr1) s[nt][2] = -1e30f;
                    if (c + 1 > qr1) s[nt][3] = -1e30f;
                }
            }

            float rm0 = -1e30f, rm1 = -1e30f;
            #pragma unroll
            for (int nt = 0; nt < 8; nt++) {
                rm0 = fmaxf(rm0, fmaxf(s[nt][0], s[nt][1]));
                rm1 = fmaxf(rm1, fmaxf(s[nt][2], s[nt][3]));
            }
            rm0 = fmaxf(rm0, __shfl_xor_sync(0xffffffffu, rm0, 1));
            rm0 = fmaxf(rm0, __shfl_xor_sync(0xffffffffu, rm0, 2));
            rm1 = fmaxf(rm1, __shfl_xor_sync(0xffffffffu, rm1, 1));
            rm1 = fmaxf(rm1, __shfl_xor_sync(0xffffffffu, rm1, 2));
            float mn0 = fmaxf(m0, rm0), mn1 = fmaxf(m1, rm1);
            float al0 = __expf(m0 - mn0), al1 = __expf(m1 - mn1);
            m0 = mn0; m1 = mn1;
            float rs0 = 0.f, rs1 = 0.f;
            #pragma unroll
            for (int nt = 0; nt < 8; nt++) {
                s[nt][0] = __expf(s[nt][0] - mn0);
                s[nt][1] = __expf(s[nt][1] - mn0);
                s[nt][2] = __expf(s[nt][2] - mn1);
                s[nt][3] = __expf(s[nt][3] - mn1);
                rs0 += s[nt][0] + s[nt][1];
                rs1 += s[nt][2] + s[nt][3];
            }
            rs0 += __shfl_xor_sync(0xffffffffu, rs0, 1);
            rs0 += __shfl_xor_sync(0xffffffffu, rs0, 2);
            rs1 += __shfl_xor_sync(0xffffffffu, rs1, 1);
            rs1 += __shfl_xor_sync(0xffffffffu, rs1, 2);
            l0 = l0 * al0 + rs0;
            l1 = l1 * al1 + rs1;
            #pragma unroll
            for (int nt = 0; nt < 8; nt++) {
                o[nt][0] *= al0; o[nt][1] *= al0;
                o[nt][2] *= al1; o[nt][3] *= al1;
            }

            uint32_t phi[4][4], plo[4][4];
            #pragma unroll
            for (int ks = 0; ks < 4; ks++) {
                phi[ks][0] = packpair(s[2 * ks][0],     s[2 * ks][1],     plo[ks][0]);
                phi[ks][1] = packpair(s[2 * ks][2],     s[2 * ks][3],     plo[ks][1]);
                phi[ks][2] = packpair(s[2 * ks + 1][0], s[2 * ks + 1][1], plo[ks][2]);
                phi[ks][3] = packpair(s[2 * ks + 1][2], s[2 * ks + 1][3], plo[ks][3]);
            }

            uint32_t vb = kb + 2 * TILE_KV;
            #pragma unroll
            for (int ks = 0; ks < 4; ks++) {
                uint32_t vhf[8][2], vlf[8][2];
                #pragma unroll
                for (int n16 = 0; n16 < 4; n16++) {
                    uint32_t ad = vb + (uint32_t)(ks * 16 + vrow_b) * RS2
                                     + (uint32_t)(n16 * 16 + vcol_b) * 2;
                    uint32_t t0, t1, t2, t3;
                    LDSM4T(t0, t1, t2, t3, ad);
                    vhf[n16 * 2][0] = t0; vhf[n16 * 2][1] = t1;
                    vhf[n16 * 2 + 1][0] = t2; vhf[n16 * 2 + 1][1] = t3;
                    LDSM4T(t0, t1, t2, t3, ad + TILE_KV);
                    vlf[n16 * 2][0] = t0; vlf[n16 * 2][1] = t1;
                    vlf[n16 * 2 + 1][0] = t2; vlf[n16 * 2 + 1][1] = t3;
                }
                #pragma unroll
                for (int nt = 0; nt < 8; nt++) MMA16816(o[nt], phi[ks], vhf[nt]);
                #pragma unroll
                for (int nt = 0; nt < 8; nt++) MMA16816(o[nt], plo[ks], vhf[nt]);
                #pragma unroll
                for (int nt = 0; nt < 8; nt++) MMA16816(o[nt], phi[ks], vlf[nt]);
            }
        }
        __syncthreads();
    }
#undef LOAD_KV

    float inv0 = 1.f / l0, inv1 = 1.f / l1;
    size_t base0 = ((size_t)(b * NUM_HEAD + h) * SEQ + qr0) * HEAD_DIM;
    size_t base1 = ((size_t)(b * NUM_HEAD + h) * SEQ + qr1) * HEAD_DIM;
    #pragma unroll
    for (int nt = 0; nt < 8; nt++) {
        int col = nt * 8 + 2 * tg;
        uint32_t lo0, lo1;
        uint32_t hi0 = packpair(o[nt][0] * inv0, o[nt][1] * inv0, lo0);
        uint32_t hi1 = packpair(o[nt][2] * inv1, o[nt][3] * inv1, lo1);
        *(uint32_t*)(ahi + base0 + col) = hi0;
        *(uint32_t*)(alo + base0 + col) = lo0;
        *(uint32_t*)(ahi + base1 + col) = hi1;
        *(uint32_t*)(alo + base1 + col) = lo1;
    }
}

// ---------------------------------------------------------------------------
extern "C" void kernel_launch(void* const* d_in, const int* in_sizes, int n_in,
                              void* d_out, int out_size)
{
    const float* x     = (const float*)d_in[0];
    const float* w_qkv = (const float*)d_in[1];
    const float* b_qkv = (const float*)d_in[2];
    const float* w_out = (const float*)d_in[3];
    const float* b_out = (const float*)d_in[4];
    float* out = (float*)d_out;

    __nv_bfloat16 *qkvhi, *qkvlo, *xhi, *xlo, *wqhi, *wqlo, *wohi, *wolo, *ahi, *alo;
    cudaGetSymbolAddress((void**)&qkvhi, g_qkvhi);
    cudaGetSymbolAddress((void**)&qkvlo, g_qkvlo);
    cudaGetSymbolAddress((void**)&xhi, g_xhi);
    cudaGetSymbolAddress((void**)&xlo, g_xlo);
    cudaGetSymbolAddress((void**)&wqhi, g_wqT_hi);
    cudaGetSymbolAddress((void**)&wqlo, g_wqT_lo);
    cudaGetSymbolAddress((void**)&wohi, g_woT_hi);
    cudaGetSymbolAddress((void**)&wolo, g_woT_lo);
    cudaGetSymbolAddress((void**)&ahi, g_ahi);
    cudaGetSymbolAddress((void**)&alo, g_alo);

    cudaFuncSetAttribute(gemm_mma, cudaFuncAttributeMaxDynamicSharedMemorySize, GEMM_SMEM);
    cudaFuncSetAttribute(flash_attn_mma, cudaFuncAttributeMaxDynamicSharedMemorySize, ATT_SMEM);

    // 0) fused prep: decompose x + both weight transposes in ONE launch
    prep_kernel<<<4096 + 3072 + 1024, 256>>>(x, xhi, xlo,
                                             w_qkv, wqhi, wqlo,
                                             w_out, wohi, wolo);

    // 1) QKV projection -> hi/lo bf16 (persistent grid)
    {
        int ntiles = (MROWS / 128) * (QKV_N / 128);   // 768
        int grid = ntiles < 296 ? ntiles : 296;
        gemm_mma<<<grid, 128, GEMM_SMEM>>>(
            xhi, xlo, wqhi, wqlo, b_qkv, nullptr, qkvhi, qkvlo, MROWS, QKV_N, D_MODEL);
    }

    // 2) causal flash attention (tensor cores) -> ahi/alo
    flash_attn_mma<<<dim3(SEQ / 128, NUM_HEAD, BATCH), 256, ATT_SMEM>>>(
        qkvhi, qkvlo, ahi, alo);

    // 3) output projection -> fp32 out
    {
        int ntiles = (MROWS / 128) * (D_MODEL / 128);  // 256
        int grid = ntiles < 296 ? ntiles : 296;
        gemm_mma<<<grid, 128, GEMM_SMEM>>>(
            ahi, alo, wohi, wolo, b_out, out, nullptr, nullptr, MROWS, D_MODEL, D_MODEL);
    }
}